// round 14
// baseline (speedup 1.0000x reference)
#include <cuda_runtime.h>
#include <cstdint>

#define BATCH   8
#define CH      512
#define HEADS   8
#define HD      64
#define GROUPS  32
#define CPG     16
#define NPIX    1024
#define EPS_GN  1e-6f
#define CHB     16
#define BK      16
#define NSPLIT  4

typedef unsigned long long ull;

// -------- scratch ----------
__device__ float g_qkv[BATCH * 3 * CH * NPIX];          // 48 MB
__device__ float g_S  [CHB * NPIX * NPIX];              // 64 MB  St[m][n] = exp(S)
__device__ float g_ao [BATCH * CH * NPIX];              // 16 MB
__device__ float g_xn [BATCH * CH * NPIX];              // 16 MB
__device__ float g_vt [BATCH * HEADS * NPIX * HD];      // 16 MB  Vt[bh][m][d]
__device__ float g_avp[NSPLIT * CHB * HD * NPIX];       // 16 MB  AV partials
__device__ float g_lp [NSPLIT * CHB * NPIX];            // row-sum partials
__device__ unsigned g_cnt[CHB * 8];                     // arrival counters (self-wrapping)
__device__ float g_wtq[CH * 3 * CH];
__device__ float g_wtp[CH * CH];

// -------- helpers ----------
__device__ __forceinline__ ull pack2(float lo, float hi) {
    ull r; asm("mov.b64 %0, {%1, %2};" : "=l"(r) : "f"(lo), "f"(hi)); return r;
}
__device__ __forceinline__ void ffma2(ull& d, ull a, ull b) {
    asm("fma.rn.f32x2 %0, %1, %2, %0;" : "+l"(d) : "l"(a), "l"(b));
}
__device__ __forceinline__ void fadd2(ull& d, ull a) {
    asm("add.rn.f32x2 %0, %0, %1;" : "+l"(d) : "l"(a));
}
__device__ __forceinline__ float f2lo(ull v) { return __uint_as_float((unsigned)v); }
__device__ __forceinline__ float f2hi(ull v) { return __uint_as_float((unsigned)(v >> 32)); }
__device__ __forceinline__ uint32_t smem_u32(const void* p) {
    uint32_t a;
    asm("{ .reg .u64 t; cvta.to.shared.u64 t, %1; cvt.u32.u64 %0, t; }" : "=r"(a) : "l"(p));
    return a;
}
__device__ __forceinline__ void cpasync16(uint32_t dst, const void* src) {
    asm volatile("cp.async.ca.shared.global [%0], [%1], 16;" :: "r"(dst), "l"(src));
}
#define CP_COMMIT() asm volatile("cp.async.commit_group;" ::: "memory")
#define CP_WAIT1()  asm volatile("cp.async.wait_group 1;" ::: "memory")
#define CP_WAIT0()  asm volatile("cp.async.wait_group 0;" ::: "memory")

// =====================================================================
// 1) Fused GroupNorm: stats + apply in one kernel (2nd pass hits L1)
// =====================================================================
__global__ void __launch_bounds__(256) gn_fused_kernel(
    const float* __restrict__ x,
    const float* __restrict__ gamma,
    const float* __restrict__ beta)
{
    const int bg = blockIdx.x;
    const int b  = bg / GROUPS;
    const int g  = bg % GROUPS;
    const int elems = CPG * NPIX;
    const float* xp = x + ((size_t)b * CH + g * CPG) * NPIX;
    float* op = g_xn + ((size_t)b * CH + g * CPG) * NPIX;

    float s = 0.f, sq = 0.f;
    for (int i = threadIdx.x; i < elems; i += 256) {
        float v = xp[i];
        s += v; sq += v * v;
    }
    #pragma unroll
    for (int o = 16; o > 0; o >>= 1) {
        s  += __shfl_xor_sync(0xffffffffu, s,  o);
        sq += __shfl_xor_sync(0xffffffffu, sq, o);
    }
    __shared__ float rs[8], rq[8];
    if ((threadIdx.x & 31) == 0) { rs[threadIdx.x >> 5] = s; rq[threadIdx.x >> 5] = sq; }
    __syncthreads();
    float S = 0.f, Q = 0.f;
    #pragma unroll
    for (int i = 0; i < 8; i++) { S += rs[i]; Q += rq[i]; }

    const float mean = S * (1.f / elems);
    const float var  = Q * (1.f / elems) - mean * mean;
    const float inv  = rsqrtf(var + EPS_GN);

    for (int i = threadIdx.x; i < elems; i += 256) {
        const int c = g * CPG + (i >> 10);
        op[i] = (xp[i] - mean) * inv * gamma[c] + beta[c];
    }
}

// 1c) weight transpose: Wt[k][m] = W[m][k]
__global__ void __launch_bounds__(256) wtrans_kernel(
    const float* __restrict__ W, float* __restrict__ Wt, int M, int K)
{
    __shared__ float tile[32][33];
    const int k0 = blockIdx.x * 32, m0 = blockIdx.y * 32;
    const int tx = threadIdx.x & 31, ty = threadIdx.x >> 5;
    #pragma unroll
    for (int r = 0; r < 32; r += 8)
        tile[ty + r][tx] = W[(size_t)(m0 + ty + r) * K + k0 + tx];
    __syncthreads();
    #pragma unroll
    for (int r = 0; r < 32; r += 8)
        Wt[(size_t)(k0 + ty + r) * M + m0 + tx] = tile[tx][ty + r];
}

// 1d) V transpose: Vt[bh][m][d] = V[bh][d][m]
__global__ void __launch_bounds__(256) vtrans_kernel()
{
    __shared__ float tile[32][33];
    const int bh = blockIdx.z;
    const int b = bh >> 3, h = bh & 7;
    const float* V = g_qkv + ((size_t)b * 3 * CH + 2 * CH + h * HD) * NPIX;
    float* Vt = g_vt + (size_t)bh * NPIX * HD;
    const int m0 = blockIdx.x * 32;
    const int d0 = blockIdx.y * 32;
    const int tx = threadIdx.x & 31, ty = threadIdx.x >> 5;
    #pragma unroll
    for (int r = 0; r < 32; r += 8)
        tile[ty + r][tx] = V[(size_t)(d0 + ty + r) * NPIX + m0 + tx];
    __syncthreads();
    #pragma unroll
    for (int r = 0; r < 32; r += 8)
        Vt[(size_t)(m0 + ty + r) * HD + d0 + tx] = tile[tx][ty + r];
}

// =====================================================================
// 2) Unified 128-thread 8x16-microtile GEMM (cp.async double-buffered)
// =====================================================================
__global__ void __launch_bounds__(128) wg128_kernel(
    const float* __restrict__ At,     // [K][Mdim]
    const float* __restrict__ bias,
    const float* __restrict__ B,      // [batch][K][NPIX]
    const float* __restrict__ res,
    float* __restrict__ C,
    int Mdim, int Kdim)
{
    __shared__ __align__(16) float As[2][BK][128];
    __shared__ __align__(16) float Bs[2][BK][128];

    const int tid = threadIdx.x;
    const int ty = tid & 15, tx = tid >> 4;
    const int bz = blockIdx.z;
    const int o0 = blockIdx.y * 128, n0 = blockIdx.x * 128;

    const float* Ab = At + o0;
    const float* Bb = B + (size_t)bz * Kdim * NPIX + n0;
    const uint32_t asb = smem_u32(As);
    const uint32_t bsb = smem_u32(Bs);

    ull acc[8][8];
    #pragma unroll
    for (int i = 0; i < 8; i++)
        #pragma unroll
        for (int j = 0; j < 8; j++) acc[i][j] = 0ull;

    #pragma unroll
    for (int s = 0; s < 4; s++) {
        int sg = tid + s * 128, r = sg >> 5, c = (sg & 31) << 2;
        cpasync16(asb + (uint32_t)((r * 128 + c) * 4), Ab + (size_t)r * Mdim + c);
        cpasync16(bsb + (uint32_t)((r * 128 + c) * 4), Bb + (size_t)r * NPIX + c);
    }
    CP_COMMIT();

    const int nt = Kdim / BK;
    for (int t = 0; t < nt; t++) {
        const int buf = t & 1;
        if (t + 1 < nt) {
            const int k0 = (t + 1) * BK, nb = buf ^ 1;
            #pragma unroll
            for (int s = 0; s < 4; s++) {
                int sg = tid + s * 128, r = sg >> 5, c = (sg & 31) << 2;
                cpasync16(asb + (uint32_t)(((nb * BK + r) * 128 + c) * 4),
                          Ab + (size_t)(k0 + r) * Mdim + c);
                cpasync16(bsb + (uint32_t)(((nb * BK + r) * 128 + c) * 4),
                          Bb + (size_t)(k0 + r) * NPIX + c);
            }
            CP_COMMIT();
            CP_WAIT1();
        } else {
            CP_WAIT0();
        }
        __syncthreads();

        #pragma unroll
        for (int kk = 0; kk < BK; kk++) {
            float4 a0 = *(const float4*)&As[buf][kk][ty * 8];
            float4 a1 = *(const float4*)&As[buf][kk][ty * 8 + 4];
            ulonglong2 b01 = *(const ulonglong2*)&Bs[buf][kk][tx * 16];
            ulonglong2 b23 = *(const ulonglong2*)&Bs[buf][kk][tx * 16 + 4];
            ulonglong2 b45 = *(const ulonglong2*)&Bs[buf][kk][tx * 16 + 8];
            ulonglong2 b67 = *(const ulonglong2*)&Bs[buf][kk][tx * 16 + 12];
            ull ap[8] = { pack2(a0.x, a0.x), pack2(a0.y, a0.y),
                          pack2(a0.z, a0.z), pack2(a0.w, a0.w),
                          pack2(a1.x, a1.x), pack2(a1.y, a1.y),
                          pack2(a1.z, a1.z), pack2(a1.w, a1.w) };
            ull bp[8] = { b01.x, b01.y, b23.x, b23.y, b45.x, b45.y, b67.x, b67.y };
            #pragma unroll
            for (int i = 0; i < 8; i++)
                #pragma unroll
                for (int j = 0; j < 8; j++)
                    ffma2(acc[i][j], ap[i], bp[j]);
        }
        __syncthreads();
    }

    float* Cb = C + (size_t)bz * Mdim * NPIX;
    const float* Rb = res ? res + (size_t)bz * Mdim * NPIX : nullptr;
    #pragma unroll
    for (int i = 0; i < 8; i++) {
        const int o = o0 + ty * 8 + i;
        const float bv = bias[o];
        float* cp = &Cb[(size_t)o * NPIX + n0 + tx * 16];
        const float* rp = Rb ? &Rb[(size_t)o * NPIX + n0 + tx * 16] : nullptr;
        #pragma unroll
        for (int j2 = 0; j2 < 4; j2++) {
            float4 v = make_float4(f2lo(acc[i][2 * j2])     + bv,
                                   f2hi(acc[i][2 * j2])     + bv,
                                   f2lo(acc[i][2 * j2 + 1]) + bv,
                                   f2hi(acc[i][2 * j2 + 1]) + bv);
            if (rp) {
                float4 q = *(const float4*)(rp + j2 * 4);
                v.x += q.x; v.y += q.y; v.z += q.z; v.w += q.w;
            }
            *(float4*)(cp + j2 * 4) = v;
        }
    }
}

// =====================================================================
// 3) QK: 2 m-tiles per CTA, Q resident in smem (loaded once).
//    Emits St[m][n] = exp(0.125 * q.k). A = K tile, B = Q (resident).
// =====================================================================
__global__ void __launch_bounds__(128) qk256_kernel(int bh0)
{
    __shared__ __align__(16) float Qs[HD][128];       // 32 KB resident
    __shared__ __align__(16) float Ks[2][BK][128];    // 16 KB streamed

    const int tid = threadIdx.x;
    const int ty = tid & 15, tx = tid >> 4;
    const int bhl = blockIdx.z;
    const int bh = bh0 + bhl;
    const int b = bh >> 3, h = bh & 7;
    const float* q = g_qkv + ((size_t)b * 3 * CH + h * HD) * NPIX;
    const float* k = g_qkv + ((size_t)b * 3 * CH + CH + h * HD) * NPIX;
    float* Sb = g_S + (size_t)bhl * NPIX * NPIX;      // St[m][n]

    const int n0 = blockIdx.x * 128;
    const uint32_t qsb = smem_u32(Qs);
    const uint32_t ksb = smem_u32(Ks);

    // prologue: resident Q (64x128) + K tile 0 of mb=0, one commit group
    #pragma unroll
    for (int s = 0; s < 16; s++) {
        int sg = tid + s * 128, r = sg >> 5, c = (sg & 31) << 2;
        cpasync16(qsb + (uint32_t)((r * 128 + c) * 4), q + (size_t)r * NPIX + n0 + c);
    }
    {
        const int m0 = blockIdx.y * 256;
        #pragma unroll
        for (int s = 0; s < 4; s++) {
            int sg = tid + s * 128, r = sg >> 5, c = (sg & 31) << 2;
            cpasync16(ksb + (uint32_t)((r * 128 + c) * 4), k + (size_t)r * NPIX + m0 + c);
        }
    }
    CP_COMMIT();

    const float scale = 0.125f;
    const int nt = HD / BK;   // 4

    #pragma unroll
    for (int mb = 0; mb < 2; mb++) {
        const int m0 = blockIdx.y * 256 + mb * 128;
        const float* Ab = k + m0;

        if (mb == 1) {   // prologue K tile 0 of mb=1 (Ks[0] free after mb=0)
            #pragma unroll
            for (int s = 0; s < 4; s++) {
                int sg = tid + s * 128, r = sg >> 5, c = (sg & 31) << 2;
                cpasync16(ksb + (uint32_t)((r * 128 + c) * 4), Ab + (size_t)r * NPIX + c);
            }
            CP_COMMIT();
        }

        ull acc[8][8];
        #pragma unroll
        for (int i = 0; i < 8; i++)
            #pragma unroll
            for (int j = 0; j < 8; j++) acc[i][j] = 0ull;

        for (int t = 0; t < nt; t++) {
            const int buf = t & 1;
            if (t + 1 < nt) {
                const int k0 = (t + 1) * BK, nb = buf ^ 1;
                #pragma unroll
                for (int s = 0; s < 4; s++) {
                    int sg = tid + s * 128, r = sg >> 5, c = (sg & 31) << 2;
                    cpasync16(ksb + (uint32_t)(((nb * BK + r) * 128 + c) * 4),
                              Ab + (size_t)(k0 + r) * NPIX + c);
                }
                CP_COMMIT();
                CP_WAIT1();
            } else {
                CP_WAIT0();
            }
            __syncthreads();

            #pragma unroll
            for (int kk = 0; kk < BK; kk++) {
                float4 a0 = *(const float4*)&Ks[buf][kk][ty * 8];
                float4 a1 = *(const float4*)&Ks[buf][kk][ty * 8 + 4];
                const float* qrow = &Qs[t * BK + kk][tx * 16];
                ulonglong2 b01 = *(const ulonglong2*)(qrow);
                ulonglong2 b23 = *(const ulonglong2*)(qrow + 4);
                ulonglong2 b45 = *(const ulonglong2*)(qrow + 8);
                ulonglong2 b67 = *(const ulonglong2*)(qrow + 12);
                ull ap[8] = { pack2(a0.x, a0.x), pack2(a0.y, a0.y),
                              pack2(a0.z, a0.z), pack2(a0.w, a0.w),
                              pack2(a1.x, a1.x), pack2(a1.y, a1.y),
                              pack2(a1.z, a1.z), pack2(a1.w, a1.w) };
                ull bp[8] = { b01.x, b01.y, b23.x, b23.y, b45.x, b45.y, b67.x, b67.y };
                #pragma unroll
                for (int i = 0; i < 8; i++)
                    #pragma unroll
                    for (int j = 0; j < 8; j++)
                        ffma2(acc[i][j], ap[i], bp[j]);
            }
            __syncthreads();
        }

        #pragma unroll
        for (int i = 0; i < 8; i++) {
            const int m = m0 + ty * 8 + i;
            float* sp = &Sb[(size_t)m * NPIX + n0 + tx * 16];
            #pragma unroll
            for (int j2 = 0; j2 < 4; j2++) {
                float4 v = make_float4(__expf(f2lo(acc[i][2 * j2])     * scale),
                                       __expf(f2hi(acc[i][2 * j2])     * scale),
                                       __expf(f2lo(acc[i][2 * j2 + 1]) * scale),
                                       __expf(f2hi(acc[i][2 * j2 + 1]) * scale));
                *(float4*)(sp + j2 * 4) = v;
            }
        }
    }
}

// =====================================================================
// 4) AV partial (m-split x NSPLIT) + fused last-CTA reduction/normalize.
// =====================================================================
__global__ void __launch_bounds__(128) av128_kernel(int bh0)
{
    __shared__ __align__(16) float Ss[2][BK][128];
    __shared__ __align__(16) float Vs[2][BK][64];
    __shared__ int sWin;

    const int tid = threadIdx.x;
    const int ty = tid & 15;        // 16 n-groups of 8
    const int tx = tid >> 4;        // 8 d-groups of 8
    const int bhl = blockIdx.y;
    const int split = blockIdx.z;
    const int bh = bh0 + bhl;
    const int b = bh >> 3, h = bh & 7;
    const int n0 = blockIdx.x * 128;
    const int m_start = split * (NPIX / NSPLIT);

    const float* St = g_S + (size_t)bhl * NPIX * NPIX + (size_t)m_start * NPIX + n0;
    const float* Vt = g_vt + ((size_t)bh * NPIX + m_start) * HD;
    float* avp = g_avp + ((size_t)split * CHB + bhl) * HD * NPIX;
    float* lp  = g_lp  + ((size_t)split * CHB + bhl) * NPIX;

    const uint32_t ssb = smem_u32(Ss);
    const uint32_t vsb = smem_u32(Vs);

    ull acc[4][8];
    #pragma unroll
    for (int i = 0; i < 4; i++)
        #pragma unroll
        for (int j = 0; j < 8; j++) acc[i][j] = 0ull;
    ull ls[4] = {0ull, 0ull, 0ull, 0ull};

    #pragma unroll
    for (int s = 0; s < 4; s++) {
        int sg = tid + s * 128, r = sg >> 5, c = (sg & 31) << 2;
        cpasync16(ssb + (uint32_t)((r * 128 + c) * 4), St + (size_t)r * NPIX + c);
    }
    #pragma unroll
    for (int s = 0; s < 2; s++) {
        int sg = tid + s * 128, r = sg >> 4, c = (sg & 15) << 2;
        cpasync16(vsb + (uint32_t)((r * 64 + c) * 4), Vt + (size_t)r * HD + c);
    }
    CP_COMMIT();

    const int nt = (NPIX / NSPLIT) / BK;   // 16
    for (int t = 0; t < nt; t++) {
        const int buf = t & 1;
        if (t + 1 < nt) {
            const int k0 = (t + 1) * BK, nb = buf ^ 1;
            #pragma unroll
            for (int s = 0; s < 4; s++) {
                int sg = tid + s * 128, r = sg >> 5, c = (sg & 31) << 2;
                cpasync16(ssb + (uint32_t)(((nb * BK + r) * 128 + c) * 4),
                          St + (size_t)(k0 + r) * NPIX + c);
            }
            #pragma unroll
            for (int s = 0; s < 2; s++) {
                int sg = tid + s * 128, r = sg >> 4, c = (sg & 15) << 2;
                cpasync16(vsb + (uint32_t)(((nb * BK + r) * 64 + c) * 4),
                          Vt + (size_t)(k0 + r) * HD + c);
            }
            CP_COMMIT();
            CP_WAIT1();
        } else {
            CP_WAIT0();
        }
        __syncthreads();

        #pragma unroll
        for (int kk = 0; kk < BK; kk++) {
            ulonglong2 s01 = *(const ulonglong2*)&Ss[buf][kk][ty * 8];
            ulonglong2 s23 = *(const ulonglong2*)&Ss[buf][kk][ty * 8 + 4];
            float4 v0 = *(const float4*)&Vs[buf][kk][tx * 8];
            float4 v1 = *(const float4*)&Vs[buf][kk][tx * 8 + 4];
            ull sp_[4] = { s01.x, s01.y, s23.x, s23.y };
            ull vd[8] = { pack2(v0.x, v0.x), pack2(v0.y, v0.y),
                          pack2(v0.z, v0.z), pack2(v0.w, v0.w),
                          pack2(v1.x, v1.x), pack2(v1.y, v1.y),
                          pack2(v1.z, v1.z), pack2(v1.w, v1.w) };
            fadd2(ls[0], sp_[0]); fadd2(ls[1], sp_[1]);
            fadd2(ls[2], sp_[2]); fadd2(ls[3], sp_[3]);
            #pragma unroll
            for (int i = 0; i < 4; i++)
                #pragma unroll
                for (int j = 0; j < 8; j++)
                    ffma2(acc[i][j], sp_[i], vd[j]);
        }
        __syncthreads();
    }

    if (tx == 0) {
        #pragma unroll
        for (int i = 0; i < 4; i++) {
            lp[n0 + ty * 8 + 2 * i]     = f2lo(ls[i]);
            lp[n0 + ty * 8 + 2 * i + 1] = f2hi(ls[i]);
        }
    }

    #pragma unroll
    for (int j = 0; j < 8; j++) {
        const int d = tx * 8 + j;
        float4 r0 = make_float4(f2lo(acc[0][j]), f2hi(acc[0][j]),
                                f2lo(acc[1][j]), f2hi(acc[1][j]));
        float4 r1 = make_float4(f2lo(acc[2][j]), f2hi(acc[2][j]),
                                f2lo(acc[3][j]), f2hi(acc[3][j]));
        float* op = &avp[(size_t)d * NPIX + n0 + ty * 8];
        *(float4*)(op)     = r0;
        *(float4*)(op + 4) = r1;
    }

    // ---- last-arriving CTA reduces the NSPLIT partials + normalizes ----
    __threadfence();
    __syncthreads();
    if (tid == 0) {
        // atomicInc wraps to 0 at NSPLIT-1 -> counter self-resets (graph-safe)
        unsigned old = atomicInc(&g_cnt[bhl * 8 + blockIdx.x], NSPLIT - 1);
        sWin = (old == NSPLIT - 1);
    }
    __syncthreads();
    if (!sWin) return;

    const int nn = n0 + tid;   // 128 threads <-> 128 n columns
    float lsum = 0.f;
    #pragma unroll
    for (int s = 0; s < NSPLIT; s++)
        lsum += g_lp[(s * CHB + bhl) * NPIX + nn];
    const float inv = 1.f / lsum;

    float* aob = g_ao + ((size_t)b * CH + h * HD) * NPIX;
    #pragma unroll 4
    for (int d = 0; d < HD; d++) {
        float p = 0.f;
        #pragma unroll
        for (int s = 0; s < NSPLIT; s++)
            p += g_avp[(((size_t)s * CHB + bhl) * HD + d) * NPIX + nn];
        aob[(size_t)d * NPIX + nn] = p * inv;
    }
}

// =====================================================================
// launcher
// =====================================================================
extern "C" void kernel_launch(void* const* d_in, const int* in_sizes, int n_in,
                              void* d_out, int out_size)
{
    const float* x      = (const float*)d_in[0];
    const float* norm_w = (const float*)d_in[1];
    const float* norm_b = (const float*)d_in[2];
    const float* qkv_w  = (const float*)d_in[3];
    const float* qkv_b  = (const float*)d_in[4];
    const float* proj_w = (const float*)d_in[5];
    const float* proj_b = (const float*)d_in[6];
    float* out = (float*)d_out;

    float *qkv_p, *ao_p, *xn_p, *wtq_p, *wtp_p;
    cudaGetSymbolAddress((void**)&qkv_p, g_qkv);
    cudaGetSymbolAddress((void**)&ao_p,  g_ao);
    cudaGetSymbolAddress((void**)&xn_p,  g_xn);
    cudaGetSymbolAddress((void**)&wtq_p, g_wtq);
    cudaGetSymbolAddress((void**)&wtp_p, g_wtp);

    // 1) fused GroupNorm + weight transposes
    gn_fused_kernel<<<BATCH * GROUPS, 256>>>(x, norm_w, norm_b);
    {
        dim3 g1(CH / 32, 3 * CH / 32);
        wtrans_kernel<<<g1, 256>>>(qkv_w, wtq_p, 3 * CH, CH);
        dim3 g2(CH / 32, CH / 32);
        wtrans_kernel<<<g2, 256>>>(proj_w, wtp_p, CH, CH);
    }

    // 2) QKV projection: M=1536, K=512
    {
        dim3 grid(NPIX / 128, (3 * CH) / 128, BATCH);
        wg128_kernel<<<grid, 128>>>(wtq_p, qkv_b, xn_p, nullptr, qkv_p, 3 * CH, CH);
    }

    // 2b) transpose V for all heads
    {
        dim3 grid(NPIX / 32, HD / 32, BATCH * HEADS);
        vtrans_kernel<<<grid, 256>>>();
    }

    // 3) attention chunks: QK (2 m-tiles/CTA) -> AV + fused reduce
    for (int bh0 = 0; bh0 < BATCH * HEADS; bh0 += CHB) {
        {
            dim3 grid(NPIX / 128, NPIX / 256, CHB);
            qk256_kernel<<<grid, 128>>>(bh0);
        }
        {
            dim3 grid(NPIX / 128, CHB, NSPLIT);
            av128_kernel<<<grid, 128>>>(bh0);
        }
    }

    // 4) proj + bias + residual: M=512, K=512
    {
        dim3 grid(NPIX / 128, CH / 128, BATCH);
        wg128_kernel<<<grid, 128>>>(wtp_p, proj_b, ao_p, x, out, CH, CH);
    }
}

// round 15
// speedup vs baseline: 1.0940x; 1.0940x over previous
#include <cuda_runtime.h>
#include <cstdint>

#define BATCH   8
#define CH      512
#define HEADS   8
#define HD      64
#define GROUPS  32
#define CPG     16
#define NPIX    1024
#define EPS_GN  1e-6f
#define CHB     16
#define BK      16
#define NSPLIT  4

typedef unsigned long long ull;

// -------- scratch ----------
__device__ float g_qkv[BATCH * 3 * CH * NPIX];          // 48 MB
__device__ float g_S  [CHB * NPIX * NPIX];              // 64 MB  St[m][n] = exp(S)
__device__ float g_ao [BATCH * CH * NPIX];              // 16 MB
__device__ float g_xn [BATCH * CH * NPIX];              // 16 MB
__device__ float g_vt [BATCH * HEADS * NPIX * HD];      // 16 MB  Vt[bh][m][d]
__device__ float g_avp[NSPLIT * CHB * HD * NPIX];       // 16 MB  AV partials
__device__ float g_lp [NSPLIT * CHB * NPIX];            // row-sum partials
__device__ float g_wtq[CH * 3 * CH];
__device__ float g_wtp[CH * CH];

// -------- helpers ----------
__device__ __forceinline__ ull pack2(float lo, float hi) {
    ull r; asm("mov.b64 %0, {%1, %2};" : "=l"(r) : "f"(lo), "f"(hi)); return r;
}
__device__ __forceinline__ void ffma2(ull& d, ull a, ull b) {
    asm("fma.rn.f32x2 %0, %1, %2, %0;" : "+l"(d) : "l"(a), "l"(b));
}
__device__ __forceinline__ void fadd2(ull& d, ull a) {
    asm("add.rn.f32x2 %0, %0, %1;" : "+l"(d) : "l"(a));
}
__device__ __forceinline__ float f2lo(ull v) { return __uint_as_float((unsigned)v); }
__device__ __forceinline__ float f2hi(ull v) { return __uint_as_float((unsigned)(v >> 32)); }
__device__ __forceinline__ uint32_t smem_u32(const void* p) {
    uint32_t a;
    asm("{ .reg .u64 t; cvta.to.shared.u64 t, %1; cvt.u32.u64 %0, t; }" : "=r"(a) : "l"(p));
    return a;
}
__device__ __forceinline__ void cpasync16(uint32_t dst, const void* src) {
    asm volatile("cp.async.ca.shared.global [%0], [%1], 16;" :: "r"(dst), "l"(src));
}
#define CP_COMMIT() asm volatile("cp.async.commit_group;" ::: "memory")
#define CP_WAIT1()  asm volatile("cp.async.wait_group 1;" ::: "memory")
#define CP_WAIT0()  asm volatile("cp.async.wait_group 0;" ::: "memory")

// =====================================================================
// 1) Fused GroupNorm: stats + apply in one kernel
// =====================================================================
__global__ void __launch_bounds__(256) gn_fused_kernel(
    const float* __restrict__ x,
    const float* __restrict__ gamma,
    const float* __restrict__ beta)
{
    const int bg = blockIdx.x;
    const int b  = bg / GROUPS;
    const int g  = bg % GROUPS;
    const int elems = CPG * NPIX;
    const float* xp = x + ((size_t)b * CH + g * CPG) * NPIX;
    float* op = g_xn + ((size_t)b * CH + g * CPG) * NPIX;

    float s = 0.f, sq = 0.f;
    for (int i = threadIdx.x; i < elems; i += 256) {
        float v = xp[i];
        s += v; sq += v * v;
    }
    #pragma unroll
    for (int o = 16; o > 0; o >>= 1) {
        s  += __shfl_xor_sync(0xffffffffu, s,  o);
        sq += __shfl_xor_sync(0xffffffffu, sq, o);
    }
    __shared__ float rs[8], rq[8];
    if ((threadIdx.x & 31) == 0) { rs[threadIdx.x >> 5] = s; rq[threadIdx.x >> 5] = sq; }
    __syncthreads();
    float S = 0.f, Q = 0.f;
    #pragma unroll
    for (int i = 0; i < 8; i++) { S += rs[i]; Q += rq[i]; }

    const float mean = S * (1.f / elems);
    const float var  = Q * (1.f / elems) - mean * mean;
    const float inv  = rsqrtf(var + EPS_GN);

    for (int i = threadIdx.x; i < elems; i += 256) {
        const int c = g * CPG + (i >> 10);
        op[i] = (xp[i] - mean) * inv * gamma[c] + beta[c];
    }
}

// 1c) weight transpose: Wt[k][m] = W[m][k]
__global__ void __launch_bounds__(256) wtrans_kernel(
    const float* __restrict__ W, float* __restrict__ Wt, int M, int K)
{
    __shared__ float tile[32][33];
    const int k0 = blockIdx.x * 32, m0 = blockIdx.y * 32;
    const int tx = threadIdx.x & 31, ty = threadIdx.x >> 5;
    #pragma unroll
    for (int r = 0; r < 32; r += 8)
        tile[ty + r][tx] = W[(size_t)(m0 + ty + r) * K + k0 + tx];
    __syncthreads();
    #pragma unroll
    for (int r = 0; r < 32; r += 8)
        Wt[(size_t)(k0 + ty + r) * M + m0 + tx] = tile[tx][ty + r];
}

// 1d) V transpose: Vt[bh][m][d] = V[bh][d][m]
__global__ void __launch_bounds__(256) vtrans_kernel()
{
    __shared__ float tile[32][33];
    const int bh = blockIdx.z;
    const int b = bh >> 3, h = bh & 7;
    const float* V = g_qkv + ((size_t)b * 3 * CH + 2 * CH + h * HD) * NPIX;
    float* Vt = g_vt + (size_t)bh * NPIX * HD;
    const int m0 = blockIdx.x * 32;
    const int d0 = blockIdx.y * 32;
    const int tx = threadIdx.x & 31, ty = threadIdx.x >> 5;
    #pragma unroll
    for (int r = 0; r < 32; r += 8)
        tile[ty + r][tx] = V[(size_t)(d0 + ty + r) * NPIX + m0 + tx];
    __syncthreads();
    #pragma unroll
    for (int r = 0; r < 32; r += 8)
        Vt[(size_t)(m0 + ty + r) * HD + d0 + tx] = tile[tx][ty + r];
}

// =====================================================================
// 2) Unified 128-thread 8x16-microtile GEMM (cp.async double-buffered)
// =====================================================================
__global__ void __launch_bounds__(128) wg128_kernel(
    const float* __restrict__ At,     // [K][Mdim]
    const float* __restrict__ bias,
    const float* __restrict__ B,      // [batch][K][NPIX]
    const float* __restrict__ res,
    float* __restrict__ C,
    int Mdim, int Kdim)
{
    __shared__ __align__(16) float As[2][BK][128];
    __shared__ __align__(16) float Bs[2][BK][128];

    const int tid = threadIdx.x;
    const int ty = tid & 15, tx = tid >> 4;
    const int bz = blockIdx.z;
    const int o0 = blockIdx.y * 128, n0 = blockIdx.x * 128;

    const float* Ab = At + o0;
    const float* Bb = B + (size_t)bz * Kdim * NPIX + n0;
    const uint32_t asb = smem_u32(As);
    const uint32_t bsb = smem_u32(Bs);

    ull acc[8][8];
    #pragma unroll
    for (int i = 0; i < 8; i++)
        #pragma unroll
        for (int j = 0; j < 8; j++) acc[i][j] = 0ull;

    #pragma unroll
    for (int s = 0; s < 4; s++) {
        int sg = tid + s * 128, r = sg >> 5, c = (sg & 31) << 2;
        cpasync16(asb + (uint32_t)((r * 128 + c) * 4), Ab + (size_t)r * Mdim + c);
        cpasync16(bsb + (uint32_t)((r * 128 + c) * 4), Bb + (size_t)r * NPIX + c);
    }
    CP_COMMIT();

    const int nt = Kdim / BK;
    for (int t = 0; t < nt; t++) {
        const int buf = t & 1;
        if (t + 1 < nt) {
            const int k0 = (t + 1) * BK, nb = buf ^ 1;
            #pragma unroll
            for (int s = 0; s < 4; s++) {
                int sg = tid + s * 128, r = sg >> 5, c = (sg & 31) << 2;
                cpasync16(asb + (uint32_t)(((nb * BK + r) * 128 + c) * 4),
                          Ab + (size_t)(k0 + r) * Mdim + c);
                cpasync16(bsb + (uint32_t)(((nb * BK + r) * 128 + c) * 4),
                          Bb + (size_t)(k0 + r) * NPIX + c);
            }
            CP_COMMIT();
            CP_WAIT1();
        } else {
            CP_WAIT0();
        }
        __syncthreads();

        #pragma unroll
        for (int kk = 0; kk < BK; kk++) {
            float4 a0 = *(const float4*)&As[buf][kk][ty * 8];
            float4 a1 = *(const float4*)&As[buf][kk][ty * 8 + 4];
            ulonglong2 b01 = *(const ulonglong2*)&Bs[buf][kk][tx * 16];
            ulonglong2 b23 = *(const ulonglong2*)&Bs[buf][kk][tx * 16 + 4];
            ulonglong2 b45 = *(const ulonglong2*)&Bs[buf][kk][tx * 16 + 8];
            ulonglong2 b67 = *(const ulonglong2*)&Bs[buf][kk][tx * 16 + 12];
            ull ap[8] = { pack2(a0.x, a0.x), pack2(a0.y, a0.y),
                          pack2(a0.z, a0.z), pack2(a0.w, a0.w),
                          pack2(a1.x, a1.x), pack2(a1.y, a1.y),
                          pack2(a1.z, a1.z), pack2(a1.w, a1.w) };
            ull bp[8] = { b01.x, b01.y, b23.x, b23.y, b45.x, b45.y, b67.x, b67.y };
            #pragma unroll
            for (int i = 0; i < 8; i++)
                #pragma unroll
                for (int j = 0; j < 8; j++)
                    ffma2(acc[i][j], ap[i], bp[j]);
        }
        __syncthreads();
    }

    float* Cb = C + (size_t)bz * Mdim * NPIX;
    const float* Rb = res ? res + (size_t)bz * Mdim * NPIX : nullptr;
    #pragma unroll
    for (int i = 0; i < 8; i++) {
        const int o = o0 + ty * 8 + i;
        const float bv = bias[o];
        float* cp = &Cb[(size_t)o * NPIX + n0 + tx * 16];
        const float* rp = Rb ? &Rb[(size_t)o * NPIX + n0 + tx * 16] : nullptr;
        #pragma unroll
        for (int j2 = 0; j2 < 4; j2++) {
            float4 v = make_float4(f2lo(acc[i][2 * j2])     + bv,
                                   f2hi(acc[i][2 * j2])     + bv,
                                   f2lo(acc[i][2 * j2 + 1]) + bv,
                                   f2hi(acc[i][2 * j2 + 1]) + bv);
            if (rp) {
                float4 q = *(const float4*)(rp + j2 * 4);
                v.x += q.x; v.y += q.y; v.z += q.z; v.w += q.w;
            }
            *(float4*)(cp + j2 * 4) = v;
        }
    }
}

// =====================================================================
// 3) QK: 2 m-tiles per CTA, Q resident in smem (loaded once).
//    Emits St[m][n] = exp(0.125 * q.k). A = K tile, B = Q (resident).
// =====================================================================
__global__ void __launch_bounds__(128) qk256_kernel(int bh0)
{
    __shared__ __align__(16) float Qs[HD][128];       // 32 KB resident
    __shared__ __align__(16) float Ks[2][BK][128];    // 16 KB streamed

    const int tid = threadIdx.x;
    const int ty = tid & 15, tx = tid >> 4;
    const int bhl = blockIdx.z;
    const int bh = bh0 + bhl;
    const int b = bh >> 3, h = bh & 7;
    const float* q = g_qkv + ((size_t)b * 3 * CH + h * HD) * NPIX;
    const float* k = g_qkv + ((size_t)b * 3 * CH + CH + h * HD) * NPIX;
    float* Sb = g_S + (size_t)bhl * NPIX * NPIX;      // St[m][n]

    const int n0 = blockIdx.x * 128;
    const uint32_t qsb = smem_u32(Qs);
    const uint32_t ksb = smem_u32(Ks);

    // prologue: resident Q (64x128) + K tile 0 of mb=0, one commit group
    #pragma unroll
    for (int s = 0; s < 16; s++) {
        int sg = tid + s * 128, r = sg >> 5, c = (sg & 31) << 2;
        cpasync16(qsb + (uint32_t)((r * 128 + c) * 4), q + (size_t)r * NPIX + n0 + c);
    }
    {
        const int m0 = blockIdx.y * 256;
        #pragma unroll
        for (int s = 0; s < 4; s++) {
            int sg = tid + s * 128, r = sg >> 5, c = (sg & 31) << 2;
            cpasync16(ksb + (uint32_t)((r * 128 + c) * 4), k + (size_t)r * NPIX + m0 + c);
        }
    }
    CP_COMMIT();

    const float scale = 0.125f;
    const int nt = HD / BK;   // 4

    #pragma unroll
    for (int mb = 0; mb < 2; mb++) {
        const int m0 = blockIdx.y * 256 + mb * 128;
        const float* Ab = k + m0;

        if (mb == 1) {   // prologue K tile 0 of mb=1 (Ks[0] free after mb=0)
            #pragma unroll
            for (int s = 0; s < 4; s++) {
                int sg = tid + s * 128, r = sg >> 5, c = (sg & 31) << 2;
                cpasync16(ksb + (uint32_t)((r * 128 + c) * 4), Ab + (size_t)r * NPIX + c);
            }
            CP_COMMIT();
        }

        ull acc[8][8];
        #pragma unroll
        for (int i = 0; i < 8; i++)
            #pragma unroll
            for (int j = 0; j < 8; j++) acc[i][j] = 0ull;

        for (int t = 0; t < nt; t++) {
            const int buf = t & 1;
            if (t + 1 < nt) {
                const int k0 = (t + 1) * BK, nb = buf ^ 1;
                #pragma unroll
                for (int s = 0; s < 4; s++) {
                    int sg = tid + s * 128, r = sg >> 5, c = (sg & 31) << 2;
                    cpasync16(ksb + (uint32_t)(((nb * BK + r) * 128 + c) * 4),
                              Ab + (size_t)(k0 + r) * NPIX + c);
                }
                CP_COMMIT();
                CP_WAIT1();
            } else {
                CP_WAIT0();
            }
            __syncthreads();

            #pragma unroll
            for (int kk = 0; kk < BK; kk++) {
                float4 a0 = *(const float4*)&Ks[buf][kk][ty * 8];
                float4 a1 = *(const float4*)&Ks[buf][kk][ty * 8 + 4];
                const float* qrow = &Qs[t * BK + kk][tx * 16];
                ulonglong2 b01 = *(const ulonglong2*)(qrow);
                ulonglong2 b23 = *(const ulonglong2*)(qrow + 4);
                ulonglong2 b45 = *(const ulonglong2*)(qrow + 8);
                ulonglong2 b67 = *(const ulonglong2*)(qrow + 12);
                ull ap[8] = { pack2(a0.x, a0.x), pack2(a0.y, a0.y),
                              pack2(a0.z, a0.z), pack2(a0.w, a0.w),
                              pack2(a1.x, a1.x), pack2(a1.y, a1.y),
                              pack2(a1.z, a1.z), pack2(a1.w, a1.w) };
                ull bp[8] = { b01.x, b01.y, b23.x, b23.y, b45.x, b45.y, b67.x, b67.y };
                #pragma unroll
                for (int i = 0; i < 8; i++)
                    #pragma unroll
                    for (int j = 0; j < 8; j++)
                        ffma2(acc[i][j], ap[i], bp[j]);
            }
            __syncthreads();
        }

        #pragma unroll
        for (int i = 0; i < 8; i++) {
            const int m = m0 + ty * 8 + i;
            float* sp = &Sb[(size_t)m * NPIX + n0 + tx * 16];
            #pragma unroll
            for (int j2 = 0; j2 < 4; j2++) {
                float4 v = make_float4(__expf(f2lo(acc[i][2 * j2])     * scale),
                                       __expf(f2hi(acc[i][2 * j2])     * scale),
                                       __expf(f2lo(acc[i][2 * j2 + 1]) * scale),
                                       __expf(f2hi(acc[i][2 * j2 + 1]) * scale));
                *(float4*)(sp + j2 * 4) = v;
            }
        }
    }
}

// =====================================================================
// 4) AV partial (m-split x NSPLIT), cp.async pipelined (R12 version)
// =====================================================================
__global__ void __launch_bounds__(128) av128_kernel(int bh0)
{
    __shared__ __align__(16) float Ss[2][BK][128];
    __shared__ __align__(16) float Vs[2][BK][64];

    const int tid = threadIdx.x;
    const int ty = tid & 15;        // 16 n-groups of 8
    const int tx = tid >> 4;        // 8 d-groups of 8
    const int bhl = blockIdx.y;
    const int split = blockIdx.z;
    const int bh = bh0 + bhl;
    const int n0 = blockIdx.x * 128;
    const int m_start = split * (NPIX / NSPLIT);

    const float* St = g_S + (size_t)bhl * NPIX * NPIX + (size_t)m_start * NPIX + n0;
    const float* Vt = g_vt + ((size_t)bh * NPIX + m_start) * HD;
    float* avp = g_avp + ((size_t)split * CHB + bhl) * HD * NPIX;
    float* lp  = g_lp  + ((size_t)split * CHB + bhl) * NPIX;

    const uint32_t ssb = smem_u32(Ss);
    const uint32_t vsb = smem_u32(Vs);

    ull acc[4][8];
    #pragma unroll
    for (int i = 0; i < 4; i++)
        #pragma unroll
        for (int j = 0; j < 8; j++) acc[i][j] = 0ull;
    ull ls[4] = {0ull, 0ull, 0ull, 0ull};

    #pragma unroll
    for (int s = 0; s < 4; s++) {
        int sg = tid + s * 128, r = sg >> 5, c = (sg & 31) << 2;
        cpasync16(ssb + (uint32_t)((r * 128 + c) * 4), St + (size_t)r * NPIX + c);
    }
    #pragma unroll
    for (int s = 0; s < 2; s++) {
        int sg = tid + s * 128, r = sg >> 4, c = (sg & 15) << 2;
        cpasync16(vsb + (uint32_t)((r * 64 + c) * 4), Vt + (size_t)r * HD + c);
    }
    CP_COMMIT();

    const int nt = (NPIX / NSPLIT) / BK;   // 16
    for (int t = 0; t < nt; t++) {
        const int buf = t & 1;
        if (t + 1 < nt) {
            const int k0 = (t + 1) * BK, nb = buf ^ 1;
            #pragma unroll
            for (int s = 0; s < 4; s++) {
                int sg = tid + s * 128, r = sg >> 5, c = (sg & 31) << 2;
                cpasync16(ssb + (uint32_t)(((nb * BK + r) * 128 + c) * 4),
                          St + (size_t)(k0 + r) * NPIX + c);
            }
            #pragma unroll
            for (int s = 0; s < 2; s++) {
                int sg = tid + s * 128, r = sg >> 4, c = (sg & 15) << 2;
                cpasync16(vsb + (uint32_t)(((nb * BK + r) * 64 + c) * 4),
                          Vt + (size_t)(k0 + r) * HD + c);
            }
            CP_COMMIT();
            CP_WAIT1();
        } else {
            CP_WAIT0();
        }
        __syncthreads();

        #pragma unroll
        for (int kk = 0; kk < BK; kk++) {
            ulonglong2 s01 = *(const ulonglong2*)&Ss[buf][kk][ty * 8];
            ulonglong2 s23 = *(const ulonglong2*)&Ss[buf][kk][ty * 8 + 4];
            float4 v0 = *(const float4*)&Vs[buf][kk][tx * 8];
            float4 v1 = *(const float4*)&Vs[buf][kk][tx * 8 + 4];
            ull sp_[4] = { s01.x, s01.y, s23.x, s23.y };
            ull vd[8] = { pack2(v0.x, v0.x), pack2(v0.y, v0.y),
                          pack2(v0.z, v0.z), pack2(v0.w, v0.w),
                          pack2(v1.x, v1.x), pack2(v1.y, v1.y),
                          pack2(v1.z, v1.z), pack2(v1.w, v1.w) };
            fadd2(ls[0], sp_[0]); fadd2(ls[1], sp_[1]);
            fadd2(ls[2], sp_[2]); fadd2(ls[3], sp_[3]);
            #pragma unroll
            for (int i = 0; i < 4; i++)
                #pragma unroll
                for (int j = 0; j < 8; j++)
                    ffma2(acc[i][j], sp_[i], vd[j]);
        }
        __syncthreads();
    }

    if (tx == 0) {
        #pragma unroll
        for (int i = 0; i < 4; i++) {
            lp[n0 + ty * 8 + 2 * i]     = f2lo(ls[i]);
            lp[n0 + ty * 8 + 2 * i + 1] = f2hi(ls[i]);
        }
    }

    #pragma unroll
    for (int j = 0; j < 8; j++) {
        const int d = tx * 8 + j;
        float4 r0 = make_float4(f2lo(acc[0][j]), f2hi(acc[0][j]),
                                f2lo(acc[1][j]), f2hi(acc[1][j]));
        float4 r1 = make_float4(f2lo(acc[2][j]), f2hi(acc[2][j]),
                                f2lo(acc[3][j]), f2hi(acc[3][j]));
        float* op = &avp[(size_t)d * NPIX + n0 + ty * 8];
        *(float4*)(op)     = r0;
        *(float4*)(op + 4) = r1;
    }
}

// 4b) reduce partials + normalize: ao = (sum_s p_s)/(sum_s l_s)
__global__ void __launch_bounds__(256) av_reduce_kernel(int bh0)
{
    const size_t SP = (size_t)CHB * HD * NPIX;
    const int i4 = blockIdx.x * 256 + threadIdx.x;
    const int e  = i4 * 4;
    const int bhl = e >> 16;
    const int rem = e & 65535;
    const int d   = rem >> 10;
    const int n   = rem & 1023;
    const int bh  = bh0 + bhl;
    const int b = bh >> 3, h = bh & 7;

    float4 p = make_float4(0.f, 0.f, 0.f, 0.f);
    float4 l = make_float4(0.f, 0.f, 0.f, 0.f);
    const int lbase = bhl * NPIX + n;
    #pragma unroll
    for (int s = 0; s < NSPLIT; s++) {
        float4 ps = *(const float4*)&g_avp[s * SP + e];
        float4 lsv = *(const float4*)&g_lp[s * CHB * NPIX + lbase];
        p.x += ps.x; p.y += ps.y; p.z += ps.z; p.w += ps.w;
        l.x += lsv.x; l.y += lsv.y; l.z += lsv.z; l.w += lsv.w;
    }
    float4 v;
    v.x = p.x / l.x; v.y = p.y / l.y; v.z = p.z / l.z; v.w = p.w / l.w;
    *(float4*)&g_ao[((size_t)b * CH + h * HD + d) * NPIX + n] = v;
}

// =====================================================================
// launcher
// =====================================================================
extern "C" void kernel_launch(void* const* d_in, const int* in_sizes, int n_in,
                              void* d_out, int out_size)
{
    const float* x      = (const float*)d_in[0];
    const float* norm_w = (const float*)d_in[1];
    const float* norm_b = (const float*)d_in[2];
    const float* qkv_w  = (const float*)d_in[3];
    const float* qkv_b  = (const float*)d_in[4];
    const float* proj_w = (const float*)d_in[5];
    const float* proj_b = (const float*)d_in[6];
    float* out = (float*)d_out;

    float *qkv_p, *ao_p, *xn_p, *wtq_p, *wtp_p;
    cudaGetSymbolAddress((void**)&qkv_p, g_qkv);
    cudaGetSymbolAddress((void**)&ao_p,  g_ao);
    cudaGetSymbolAddress((void**)&xn_p,  g_xn);
    cudaGetSymbolAddress((void**)&wtq_p, g_wtq);
    cudaGetSymbolAddress((void**)&wtp_p, g_wtp);

    // 1) fused GroupNorm + weight transposes
    gn_fused_kernel<<<BATCH * GROUPS, 256>>>(x, norm_w, norm_b);
    {
        dim3 g1(CH / 32, 3 * CH / 32);
        wtrans_kernel<<<g1, 256>>>(qkv_w, wtq_p, 3 * CH, CH);
        dim3 g2(CH / 32, CH / 32);
        wtrans_kernel<<<g2, 256>>>(proj_w, wtp_p, CH, CH);
    }

    // 2) QKV projection: M=1536, K=512
    {
        dim3 grid(NPIX / 128, (3 * CH) / 128, BATCH);
        wg128_kernel<<<grid, 128>>>(wtq_p, qkv_b, xn_p, nullptr, qkv_p, 3 * CH, CH);
    }

    // 2b) transpose V for all heads
    {
        dim3 grid(NPIX / 32, HD / 32, BATCH * HEADS);
        vtrans_kernel<<<grid, 256>>>();
    }

    // 3) attention chunks: QK (2 m-tiles/CTA) -> AV partials -> reduce
    for (int bh0 = 0; bh0 < BATCH * HEADS; bh0 += CHB) {
        {
            dim3 grid(NPIX / 128, NPIX / 256, CHB);
            qk256_kernel<<<grid, 128>>>(bh0);
        }
        {
            dim3 grid(NPIX / 128, CHB, NSPLIT);
            av128_kernel<<<grid, 128>>>(bh0);
        }
        av_reduce_kernel<<<CHB * HD * NPIX / 1024, 256>>>(bh0);
    }

    // 4) proj + bias + residual: M=512, K=512
    {
        dim3 grid(NPIX / 128, CH / 128, BATCH);
        wg128_kernel<<<grid, 128>>>(wtp_p, proj_b, ao_p, x, out, CH, CH);
    }
}

// round 17
// speedup vs baseline: 1.1589x; 1.0594x over previous
#include <cuda_runtime.h>
#include <cstdint>

#define BATCH   8
#define CH      512
#define HEADS   8
#define HD      64
#define GROUPS  32
#define CPG     16
#define NPIX    1024
#define EPS_GN  1e-6f
#define CHB     16
#define BK      16
#define NSPLIT  4

typedef unsigned long long ull;

// -------- scratch ----------
__device__ float g_qkv[BATCH * 3 * CH * NPIX];          // 48 MB
__device__ float g_S  [CHB * NPIX * NPIX];              // 64 MB  St[m][n] = exp(S)
__device__ float g_ao [BATCH * CH * NPIX];              // 16 MB
__device__ float g_xn [BATCH * CH * NPIX];              // 16 MB
__device__ float g_vt [BATCH * HEADS * NPIX * HD];      // 16 MB  Vt[bh][m][d]
__device__ float g_avp[NSPLIT * CHB * HD * NPIX];       // 16 MB  AV partials
__device__ float g_lp [NSPLIT * CHB * NPIX];            // row-sum partials
__device__ float g_wtq[CH * 3 * CH];
__device__ float g_wtp[CH * CH];

// -------- helpers ----------
__device__ __forceinline__ ull pack2(float lo, float hi) {
    ull r; asm("mov.b64 %0, {%1, %2};" : "=l"(r) : "f"(lo), "f"(hi)); return r;
}
__device__ __forceinline__ void ffma2(ull& d, ull a, ull b) {
    asm("fma.rn.f32x2 %0, %1, %2, %0;" : "+l"(d) : "l"(a), "l"(b));
}
__device__ __forceinline__ void fadd2(ull& d, ull a) {
    asm("add.rn.f32x2 %0, %0, %1;" : "+l"(d) : "l"(a));
}
__device__ __forceinline__ float f2lo(ull v) { return __uint_as_float((unsigned)v); }
__device__ __forceinline__ float f2hi(ull v) { return __uint_as_float((unsigned)(v >> 32)); }
__device__ __forceinline__ uint32_t smem_u32(const void* p) {
    uint32_t a;
    asm("{ .reg .u64 t; cvta.to.shared.u64 t, %1; cvt.u32.u64 %0, t; }" : "=r"(a) : "l"(p));
    return a;
}
__device__ __forceinline__ void cpasync16(uint32_t dst, const void* src) {
    asm volatile("cp.async.ca.shared.global [%0], [%1], 16;" :: "r"(dst), "l"(src));
}
#define CP_COMMIT() asm volatile("cp.async.commit_group;" ::: "memory")
#define CP_WAIT1()  asm volatile("cp.async.wait_group 1;" ::: "memory")
#define CP_WAIT0()  asm volatile("cp.async.wait_group 0;" ::: "memory")

// =====================================================================
// 1) Fused GroupNorm: stats + apply in one kernel (2nd read hits cache)
// =====================================================================
__global__ void __launch_bounds__(256) gn_fused_kernel(
    const float* __restrict__ x,
    const float* __restrict__ gamma,
    const float* __restrict__ beta)
{
    const int bg = blockIdx.x;
    const int b  = bg / GROUPS;
    const int g  = bg % GROUPS;
    const int elems = CPG * NPIX;
    const float* xp = x + ((size_t)b * CH + g * CPG) * NPIX;
    float* op = g_xn + ((size_t)b * CH + g * CPG) * NPIX;

    float s = 0.f, sq = 0.f;
    for (int i = threadIdx.x; i < elems; i += 256) {
        float v = xp[i];
        s += v; sq += v * v;
    }
    #pragma unroll
    for (int o = 16; o > 0; o >>= 1) {
        s  += __shfl_xor_sync(0xffffffffu, s,  o);
        sq += __shfl_xor_sync(0xffffffffu, sq, o);
    }
    __shared__ float rs[8], rq[8];
    if ((threadIdx.x & 31) == 0) { rs[threadIdx.x >> 5] = s; rq[threadIdx.x >> 5] = sq; }
    __syncthreads();
    float S = 0.f, Q = 0.f;
    #pragma unroll
    for (int i = 0; i < 8; i++) { S += rs[i]; Q += rq[i]; }

    const float mean = S * (1.f / elems);
    const float var  = Q * (1.f / elems) - mean * mean;
    const float inv  = rsqrtf(var + EPS_GN);

    for (int i = threadIdx.x; i < elems; i += 256) {
        const int c = g * CPG + (i >> 10);
        op[i] = (xp[i] - mean) * inv * gamma[c] + beta[c];
    }
}

// 1c) weight transpose: Wt[k][m] = W[m][k]
__global__ void __launch_bounds__(256) wtrans_kernel(
    const float* __restrict__ W, float* __restrict__ Wt, int M, int K)
{
    __shared__ float tile[32][33];
    const int k0 = blockIdx.x * 32, m0 = blockIdx.y * 32;
    const int tx = threadIdx.x & 31, ty = threadIdx.x >> 5;
    #pragma unroll
    for (int r = 0; r < 32; r += 8)
        tile[ty + r][tx] = W[(size_t)(m0 + ty + r) * K + k0 + tx];
    __syncthreads();
    #pragma unroll
    for (int r = 0; r < 32; r += 8)
        Wt[(size_t)(k0 + ty + r) * M + m0 + tx] = tile[tx][ty + r];
}

// 1d) V transpose: Vt[bh][m][d] = V[bh][d][m]
__global__ void __launch_bounds__(256) vtrans_kernel()
{
    __shared__ float tile[32][33];
    const int bh = blockIdx.z;
    const int b = bh >> 3, h = bh & 7;
    const float* V = g_qkv + ((size_t)b * 3 * CH + 2 * CH + h * HD) * NPIX;
    float* Vt = g_vt + (size_t)bh * NPIX * HD;
    const int m0 = blockIdx.x * 32;
    const int d0 = blockIdx.y * 32;
    const int tx = threadIdx.x & 31, ty = threadIdx.x >> 5;
    #pragma unroll
    for (int r = 0; r < 32; r += 8)
        tile[ty + r][tx] = V[(size_t)(d0 + ty + r) * NPIX + m0 + tx];
    __syncthreads();
    #pragma unroll
    for (int r = 0; r < 32; r += 8)
        Vt[(size_t)(m0 + ty + r) * HD + d0 + tx] = tile[tx][ty + r];
}

// =====================================================================
// 2) Unified 128-thread 8x16-microtile GEMM (cp.async double-buffered)
// =====================================================================
__global__ void __launch_bounds__(128) wg128_kernel(
    const float* __restrict__ At,     // [K][Mdim]
    const float* __restrict__ bias,
    const float* __restrict__ B,      // [batch][K][NPIX]
    const float* __restrict__ res,
    float* __restrict__ C,
    int Mdim, int Kdim)
{
    __shared__ __align__(16) float As[2][BK][128];
    __shared__ __align__(16) float Bs[2][BK][128];

    const int tid = threadIdx.x;
    const int ty = tid & 15, tx = tid >> 4;
    const int bz = blockIdx.z;
    const int o0 = blockIdx.y * 128, n0 = blockIdx.x * 128;

    const float* Ab = At + o0;
    const float* Bb = B + (size_t)bz * Kdim * NPIX + n0;
    const uint32_t asb = smem_u32(As);
    const uint32_t bsb = smem_u32(Bs);

    ull acc[8][8];
    #pragma unroll
    for (int i = 0; i < 8; i++)
        #pragma unroll
        for (int j = 0; j < 8; j++) acc[i][j] = 0ull;

    #pragma unroll
    for (int s = 0; s < 4; s++) {
        int sg = tid + s * 128, r = sg >> 5, c = (sg & 31) << 2;
        cpasync16(asb + (uint32_t)((r * 128 + c) * 4), Ab + (size_t)r * Mdim + c);
        cpasync16(bsb + (uint32_t)((r * 128 + c) * 4), Bb + (size_t)r * NPIX + c);
    }
    CP_COMMIT();

    const int nt = Kdim / BK;
    for (int t = 0; t < nt; t++) {
        const int buf = t & 1;
        if (t + 1 < nt) {
            const int k0 = (t + 1) * BK, nb = buf ^ 1;
            #pragma unroll
            for (int s = 0; s < 4; s++) {
                int sg = tid + s * 128, r = sg >> 5, c = (sg & 31) << 2;
                cpasync16(asb + (uint32_t)(((nb * BK + r) * 128 + c) * 4),
                          Ab + (size_t)(k0 + r) * Mdim + c);
                cpasync16(bsb + (uint32_t)(((nb * BK + r) * 128 + c) * 4),
                          Bb + (size_t)(k0 + r) * NPIX + c);
            }
            CP_COMMIT();
            CP_WAIT1();
        } else {
            CP_WAIT0();
        }
        __syncthreads();

        #pragma unroll
        for (int kk = 0; kk < BK; kk++) {
            float4 a0 = *(const float4*)&As[buf][kk][ty * 8];
            float4 a1 = *(const float4*)&As[buf][kk][ty * 8 + 4];
            ulonglong2 b01 = *(const ulonglong2*)&Bs[buf][kk][tx * 16];
            ulonglong2 b23 = *(const ulonglong2*)&Bs[buf][kk][tx * 16 + 4];
            ulonglong2 b45 = *(const ulonglong2*)&Bs[buf][kk][tx * 16 + 8];
            ulonglong2 b67 = *(const ulonglong2*)&Bs[buf][kk][tx * 16 + 12];
            ull ap[8] = { pack2(a0.x, a0.x), pack2(a0.y, a0.y),
                          pack2(a0.z, a0.z), pack2(a0.w, a0.w),
                          pack2(a1.x, a1.x), pack2(a1.y, a1.y),
                          pack2(a1.z, a1.z), pack2(a1.w, a1.w) };
            ull bp[8] = { b01.x, b01.y, b23.x, b23.y, b45.x, b45.y, b67.x, b67.y };
            #pragma unroll
            for (int i = 0; i < 8; i++)
                #pragma unroll
                for (int j = 0; j < 8; j++)
                    ffma2(acc[i][j], ap[i], bp[j]);
        }
        __syncthreads();
    }

    float* Cb = C + (size_t)bz * Mdim * NPIX;
    const float* Rb = res ? res + (size_t)bz * Mdim * NPIX : nullptr;
    #pragma unroll
    for (int i = 0; i < 8; i++) {
        const int o = o0 + ty * 8 + i;
        const float bv = bias[o];
        float* cp = &Cb[(size_t)o * NPIX + n0 + tx * 16];
        const float* rp = Rb ? &Rb[(size_t)o * NPIX + n0 + tx * 16] : nullptr;
        #pragma unroll
        for (int j2 = 0; j2 < 4; j2++) {
            float4 v = make_float4(f2lo(acc[i][2 * j2])     + bv,
                                   f2hi(acc[i][2 * j2])     + bv,
                                   f2lo(acc[i][2 * j2 + 1]) + bv,
                                   f2hi(acc[i][2 * j2 + 1]) + bv);
            if (rp) {
                float4 q = *(const float4*)(rp + j2 * 4);
                v.x += q.x; v.y += q.y; v.z += q.z; v.w += q.w;
            }
            *(float4*)(cp + j2 * 4) = v;
        }
    }
}

// =====================================================================
// 3) QK (K=64), emits St[m][n] = exp(0.125 * q.k)  (R12 version)
// =====================================================================
__global__ void __launch_bounds__(128) qk128_kernel(int bh0)
{
    __shared__ __align__(16) float As[2][BK][128];
    __shared__ __align__(16) float Bs[2][BK][128];

    const int tid = threadIdx.x;
    const int ty = tid & 15, tx = tid >> 4;
    const int bhl = blockIdx.z;
    const int bh = bh0 + bhl;
    const int b = bh >> 3, h = bh & 7;
    const float* q = g_qkv + ((size_t)b * 3 * CH + h * HD) * NPIX;
    const float* k = g_qkv + ((size_t)b * 3 * CH + CH + h * HD) * NPIX;
    float* Sb = g_S + (size_t)bhl * NPIX * NPIX;   // St[m][n]

    const int m0 = blockIdx.y * 128;   // A side -> output rows
    const int n0 = blockIdx.x * 128;   // B side -> output cols
    const float* Ab = k + m0;
    const float* Bb = q + n0;
    const uint32_t asb = smem_u32(As);
    const uint32_t bsb = smem_u32(Bs);

    ull acc[8][8];
    #pragma unroll
    for (int i = 0; i < 8; i++)
        #pragma unroll
        for (int j = 0; j < 8; j++) acc[i][j] = 0ull;

    #pragma unroll
    for (int s = 0; s < 4; s++) {
        int sg = tid + s * 128, r = sg >> 5, c = (sg & 31) << 2;
        cpasync16(asb + (uint32_t)((r * 128 + c) * 4), Ab + (size_t)r * NPIX + c);
        cpasync16(bsb + (uint32_t)((r * 128 + c) * 4), Bb + (size_t)r * NPIX + c);
    }
    CP_COMMIT();

    const int nt = HD / BK;
    for (int t = 0; t < nt; t++) {
        const int buf = t & 1;
        if (t + 1 < nt) {
            const int k0 = (t + 1) * BK, nb = buf ^ 1;
            #pragma unroll
            for (int s = 0; s < 4; s++) {
                int sg = tid + s * 128, r = sg >> 5, c = (sg & 31) << 2;
                cpasync16(asb + (uint32_t)(((nb * BK + r) * 128 + c) * 4),
                          Ab + (size_t)(k0 + r) * NPIX + c);
                cpasync16(bsb + (uint32_t)(((nb * BK + r) * 128 + c) * 4),
                          Bb + (size_t)(k0 + r) * NPIX + c);
            }
            CP_COMMIT();
            CP_WAIT1();
        } else {
            CP_WAIT0();
        }
        __syncthreads();

        #pragma unroll
        for (int kk = 0; kk < BK; kk++) {
            float4 a0 = *(const float4*)&As[buf][kk][ty * 8];
            float4 a1 = *(const float4*)&As[buf][kk][ty * 8 + 4];
            ulonglong2 b01 = *(const ulonglong2*)&Bs[buf][kk][tx * 16];
            ulonglong2 b23 = *(const ulonglong2*)&Bs[buf][kk][tx * 16 + 4];
            ulonglong2 b45 = *(const ulonglong2*)&Bs[buf][kk][tx * 16 + 8];
            ulonglong2 b67 = *(const ulonglong2*)&Bs[buf][kk][tx * 16 + 12];
            ull ap[8] = { pack2(a0.x, a0.x), pack2(a0.y, a0.y),
                          pack2(a0.z, a0.z), pack2(a0.w, a0.w),
                          pack2(a1.x, a1.x), pack2(a1.y, a1.y),
                          pack2(a1.z, a1.z), pack2(a1.w, a1.w) };
            ull bp[8] = { b01.x, b01.y, b23.x, b23.y, b45.x, b45.y, b67.x, b67.y };
            #pragma unroll
            for (int i = 0; i < 8; i++)
                #pragma unroll
                for (int j = 0; j < 8; j++)
                    ffma2(acc[i][j], ap[i], bp[j]);
        }
        __syncthreads();
    }

    const float scale = 0.125f;
    #pragma unroll
    for (int i = 0; i < 8; i++) {
        const int m = m0 + ty * 8 + i;
        float* sp = &Sb[(size_t)m * NPIX + n0 + tx * 16];
        #pragma unroll
        for (int j2 = 0; j2 < 4; j2++) {
            float4 v = make_float4(__expf(f2lo(acc[i][2 * j2])     * scale),
                                   __expf(f2hi(acc[i][2 * j2])     * scale),
                                   __expf(f2lo(acc[i][2 * j2 + 1]) * scale),
                                   __expf(f2hi(acc[i][2 * j2 + 1]) * scale));
            *(float4*)(sp + j2 * 4) = v;
        }
    }
}

// =====================================================================
// 4) AV partial (m-split x NSPLIT), cp.async pipelined (R12 version)
// =====================================================================
__global__ void __launch_bounds__(128) av128_kernel(int bh0)
{
    __shared__ __align__(16) float Ss[2][BK][128];
    __shared__ __align__(16) float Vs[2][BK][64];

    const int tid = threadIdx.x;
    const int ty = tid & 15;        // 16 n-groups of 8
    const int tx = tid >> 4;        // 8 d-groups of 8
    const int bhl = blockIdx.y;
    const int split = blockIdx.z;
    const int bh = bh0 + bhl;
    const int n0 = blockIdx.x * 128;
    const int m_start = split * (NPIX / NSPLIT);

    const float* St = g_S + (size_t)bhl * NPIX * NPIX + (size_t)m_start * NPIX + n0;
    const float* Vt = g_vt + ((size_t)bh * NPIX + m_start) * HD;
    float* avp = g_avp + ((size_t)split * CHB + bhl) * HD * NPIX;
    float* lp  = g_lp  + ((size_t)split * CHB + bhl) * NPIX;

    const uint32_t ssb = smem_u32(Ss);
    const uint32_t vsb = smem_u32(Vs);

    ull acc[4][8];
    #pragma unroll
    for (int i = 0; i < 4; i++)
        #pragma unroll
        for (int j = 0; j < 8; j++) acc[i][j] = 0ull;
    ull ls[4] = {0ull, 0ull, 0ull, 0ull};

    #pragma unroll
    for (int s = 0; s < 4; s++) {
        int sg = tid + s * 128, r = sg >> 5, c = (sg & 31) << 2;
        cpasync16(ssb + (uint32_t)((r * 128 + c) * 4), St + (size_t)r * NPIX + c);
    }
    #pragma unroll
    for (int s = 0; s < 2; s++) {
        int sg = tid + s * 128, r = sg >> 4, c = (sg & 15) << 2;
        cpasync16(vsb + (uint32_t)((r * 64 + c) * 4), Vt + (size_t)r * HD + c);
    }
    CP_COMMIT();

    const int nt = (NPIX / NSPLIT) / BK;   // 16
    for (int t = 0; t < nt; t++) {
        const int buf = t & 1;
        if (t + 1 < nt) {
            const int k0 = (t + 1) * BK, nb = buf ^ 1;
            #pragma unroll
            for (int s = 0; s < 4; s++) {
                int sg = tid + s * 128, r = sg >> 5, c = (sg & 31) << 2;
                cpasync16(ssb + (uint32_t)(((nb * BK + r) * 128 + c) * 4),
                          St + (size_t)(k0 + r) * NPIX + c);
            }
            #pragma unroll
            for (int s = 0; s < 2; s++) {
                int sg = tid + s * 128, r = sg >> 4, c = (sg & 15) << 2;
                cpasync16(vsb + (uint32_t)(((nb * BK + r) * 64 + c) * 4),
                          Vt + (size_t)(k0 + r) * HD + c);
            }
            CP_COMMIT();
            CP_WAIT1();
        } else {
            CP_WAIT0();
        }
        __syncthreads();

        #pragma unroll
        for (int kk = 0; kk < BK; kk++) {
            ulonglong2 s01 = *(const ulonglong2*)&Ss[buf][kk][ty * 8];
            ulonglong2 s23 = *(const ulonglong2*)&Ss[buf][kk][ty * 8 + 4];
            float4 v0 = *(const float4*)&Vs[buf][kk][tx * 8];
            float4 v1 = *(const float4*)&Vs[buf][kk][tx * 8 + 4];
            ull sp_[4] = { s01.x, s01.y, s23.x, s23.y };
            ull vd[8] = { pack2(v0.x, v0.x), pack2(v0.y, v0.y),
                          pack2(v0.z, v0.z), pack2(v0.w, v0.w),
                          pack2(v1.x, v1.x), pack2(v1.y, v1.y),
                          pack2(v1.z, v1.z), pack2(v1.w, v1.w) };
            fadd2(ls[0], sp_[0]); fadd2(ls[1], sp_[1]);
            fadd2(ls[2], sp_[2]); fadd2(ls[3], sp_[3]);
            #pragma unroll
            for (int i = 0; i < 4; i++)
                #pragma unroll
                for (int j = 0; j < 8; j++)
                    ffma2(acc[i][j], sp_[i], vd[j]);
        }
        __syncthreads();
    }

    if (tx == 0) {
        #pragma unroll
        for (int i = 0; i < 4; i++) {
            lp[n0 + ty * 8 + 2 * i]     = f2lo(ls[i]);
            lp[n0 + ty * 8 + 2 * i + 1] = f2hi(ls[i]);
        }
    }

    #pragma unroll
    for (int j = 0; j < 8; j++) {
        const int d = tx * 8 + j;
        float4 r0 = make_float4(f2lo(acc[0][j]), f2hi(acc[0][j]),
                                f2lo(acc[1][j]), f2hi(acc[1][j]));
        float4 r1 = make_float4(f2lo(acc[2][j]), f2hi(acc[2][j]),
                                f2lo(acc[3][j]), f2hi(acc[3][j]));
        float* op = &avp[(size_t)d * NPIX + n0 + ty * 8];
        *(float4*)(op)     = r0;
        *(float4*)(op + 4) = r1;
    }
}

// 4b) reduce partials + normalize: ao = (sum_s p_s)/(sum_s l_s)
__global__ void __launch_bounds__(256) av_reduce_kernel(int bh0)
{
    const size_t SP = (size_t)CHB * HD * NPIX;
    const int i4 = blockIdx.x * 256 + threadIdx.x;
    const int e  = i4 * 4;
    const int bhl = e >> 16;
    const int rem = e & 65535;
    const int d   = rem >> 10;
    const int n   = rem & 1023;
    const int bh  = bh0 + bhl;
    const int b = bh >> 3, h = bh & 7;

    float4 p = make_float4(0.f, 0.f, 0.f, 0.f);
    float4 l = make_float4(0.f, 0.f, 0.f, 0.f);
    const int lbase = bhl * NPIX + n;
    #pragma unroll
    for (int s = 0; s < NSPLIT; s++) {
        float4 ps = *(const float4*)&g_avp[s * SP + e];
        float4 lsv = *(const float4*)&g_lp[s * CHB * NPIX + lbase];
        p.x += ps.x; p.y += ps.y; p.z += ps.z; p.w += ps.w;
        l.x += lsv.x; l.y += lsv.y; l.z += lsv.z; l.w += lsv.w;
    }
    float4 v;
    v.x = p.x / l.x; v.y = p.y / l.y; v.z = p.z / l.z; v.w = p.w / l.w;
    *(float4*)&g_ao[((size_t)b * CH + h * HD + d) * NPIX + n] = v;
}

// =====================================================================
// launcher
// =====================================================================
extern "C" void kernel_launch(void* const* d_in, const int* in_sizes, int n_in,
                              void* d_out, int out_size)
{
    const float* x      = (const float*)d_in[0];
    const float* norm_w = (const float*)d_in[1];
    const float* norm_b = (const float*)d_in[2];
    const float* qkv_w  = (const float*)d_in[3];
    const float* qkv_b  = (const float*)d_in[4];
    const float* proj_w = (const float*)d_in[5];
    const float* proj_b = (const float*)d_in[6];
    float* out = (float*)d_out;

    float *qkv_p, *ao_p, *xn_p, *wtq_p, *wtp_p;
    cudaGetSymbolAddress((void**)&qkv_p, g_qkv);
    cudaGetSymbolAddress((void**)&ao_p,  g_ao);
    cudaGetSymbolAddress((void**)&xn_p,  g_xn);
    cudaGetSymbolAddress((void**)&wtq_p, g_wtq);
    cudaGetSymbolAddress((void**)&wtp_p, g_wtp);

    // 1) fused GroupNorm + weight transposes
    gn_fused_kernel<<<BATCH * GROUPS, 256>>>(x, norm_w, norm_b);
    {
        dim3 g1(CH / 32, 3 * CH / 32);
        wtrans_kernel<<<g1, 256>>>(qkv_w, wtq_p, 3 * CH, CH);
        dim3 g2(CH / 32, CH / 32);
        wtrans_kernel<<<g2, 256>>>(proj_w, wtp_p, CH, CH);
    }

    // 2) QKV projection: M=1536, K=512
    {
        dim3 grid(NPIX / 128, (3 * CH) / 128, BATCH);
        wg128_kernel<<<grid, 128>>>(wtq_p, qkv_b, xn_p, nullptr, qkv_p, 3 * CH, CH);
    }

    // 2b) transpose V for all heads
    {
        dim3 grid(NPIX / 32, HD / 32, BATCH * HEADS);
        vtrans_kernel<<<grid, 256>>>();
    }

    // 3) attention chunks: QK->St+exp, AV partials (4-way), reduce+normalize
    for (int bh0 = 0; bh0 < BATCH * HEADS; bh0 += CHB) {
        {
            dim3 grid(NPIX / 128, NPIX / 128, CHB);
            qk128_kernel<<<grid, 128>>>(bh0);
        }
        {
            dim3 grid(NPIX / 128, CHB, NSPLIT);
            av128_kernel<<<grid, 128>>>(bh0);
        }
        av_reduce_kernel<<<CHB * HD * NPIX / 1024, 256>>>(bh0);
    }

    // 4) proj + bias + residual: M=512, K=512
    {
        dim3 grid(NPIX / 128, CH / 128, BATCH);
        wg128_kernel<<<grid, 128>>>(wtp_p, proj_b, ao_p, x, out, CH, CH);
    }
}